// round 16
// baseline (speedup 1.0000x reference)
#include <cuda_runtime.h>
#include <cuda_fp16.h>
#include <cstdint>

#define Bb 16
#define Ll 2048
#define Ee 1024
#define Dk 128
#define Mtot (Bb*Ll)   // 32768

__device__ __half g_Qf[Mtot*Dk];
__device__ __half g_Kf[Mtot*Dk];
__device__ __half g_Vf[Mtot*Dk];
// Weights: [mat(3)][N=128][K=1024] fp16, pre-scaled by 32 (epilogue /32).
__device__ __half g_Wt[3 * 128 * 1024];
// Per-batch mean of valid V rows (padded-query broadcast value).
__device__ float g_meanV[Bb * Dk];

#define QSCALE 0.12751743f   /* log2(e)/sqrt(128) */

__device__ __forceinline__ uint32_t smem_u32(const void* p) {
    uint32_t a;
    asm("{ .reg .u64 t; cvta.to.shared.u64 t, %1; cvt.u32.u64 %0, t; }"
        : "=r"(a) : "l"(p));
    return a;
}

#define LDMX4(r, addr) \
    asm volatile("ldmatrix.sync.aligned.m8n8.x4.shared.b16 {%0,%1,%2,%3}, [%4];" \
        : "=r"((r)[0]), "=r"((r)[1]), "=r"((r)[2]), "=r"((r)[3]) : "r"(addr))

#define LDMX4T(r, addr) \
    asm volatile("ldmatrix.sync.aligned.m8n8.x4.trans.shared.b16 {%0,%1,%2,%3}, [%4];" \
        : "=r"((r)[0]), "=r"((r)[1]), "=r"((r)[2]), "=r"((r)[3]) : "r"(addr))

#define MMAF16(d, a, b0, b1) \
    asm volatile("mma.sync.aligned.m16n8k16.row.col.f32.f16.f16.f32 " \
        "{%0,%1,%2,%3}, {%4,%5,%6,%7}, {%8,%9}, {%0,%1,%2,%3};" \
        : "+f"((d)[0]), "+f"((d)[1]), "+f"((d)[2]), "+f"((d)[3]) \
        : "r"((a)[0]), "r"((a)[1]), "r"((a)[2]), "r"((a)[3]), "r"(b0), "r"(b1))

#define CP_COMMIT asm volatile("cp.async.commit_group;")
#define CP_WAIT(N) asm volatile("cp.async.wait_group %0;" :: "n"(N))

__device__ __forceinline__ void cpa16(uint32_t dst, const void* src) {
    asm volatile("cp.async.cg.shared.global [%0], [%1], 16;"
                 :: "r"(dst), "l"(src));
}

__device__ __forceinline__ uint32_t pack_h2(float x, float y) {
    __half2 h = __floats2half2_rn(x, y);
    return *(uint32_t*)&h;
}

// Assemble one m16n8k16 A-fragment (4 regs) from fp32 smem (given pitch).
__device__ __forceinline__ void a_frag_f32p(uint32_t* a, const char* smA,
                                            int pitch, int rb, int cb, int lane) {
    int r  = rb + (lane >> 2);
    int c  = cb + (lane & 3) * 2;
    float2 v0 = *(const float2*)(smA + r * pitch + c * 4);
    float2 v1 = *(const float2*)(smA + (r + 8) * pitch + c * 4);
    float2 v2 = *(const float2*)(smA + r * pitch + (c + 8) * 4);
    float2 v3 = *(const float2*)(smA + (r + 8) * pitch + (c + 8) * 4);
    a[0] = pack_h2(v0.x, v0.y);
    a[1] = pack_h2(v1.x, v1.y);
    a[2] = pack_h2(v2.x, v2.y);
    a[3] = pack_h2(v3.x, v3.y);
}

// ---------------------------------------------------------------------------
// Weight prep: W[1024,128] fp32 -> 32*W fp16, transposed [n][k].
// ---------------------------------------------------------------------------
__global__ void prep_weights(const float* __restrict__ Wq,
                             const float* __restrict__ Wk,
                             const float* __restrict__ Wv)
{
    __shared__ float t[32][33];
    const int mat = blockIdx.z;
    const float* W = (mat == 0) ? Wq : (mat == 1) ? Wk : Wv;
    const int k0 = blockIdx.x * 32, n0 = blockIdx.y * 32;
    const int tx = threadIdx.x, ty = threadIdx.y;
    t[ty][tx] = W[(size_t)(k0 + ty) * Dk + n0 + tx];
    __syncthreads();
    g_Wt[(size_t)mat * 131072 + (size_t)(n0 + ty) * Ee + k0 + tx] =
        __float2half_rn(t[tx][ty] * 32.0f);
}

// ---------------------------------------------------------------------------
// meanV: per batch, mean of V rows [0, len) -> g_meanV. 512 thr, 4-way split.
// ---------------------------------------------------------------------------
__global__ void mean_v(const int* __restrict__ lens)
{
    __shared__ float red[512];
    const int b    = blockIdx.x;
    const int len  = lens[b];
    const int d    = threadIdx.x & 127;
    const int part = threadIdx.x >> 7;
    float s = 0.0f;
    for (int k = part; k < len; k += 4)
        s += __half2float(g_Vf[((size_t)(b * Ll + k)) * Dk + d]);
    red[threadIdx.x] = s;
    __syncthreads();
    if (part == 0) {
        float tot = red[d] + red[d + 128] + red[d + 256] + red[d + 384];
        g_meanV[b * Dk + d] = tot / (float)len;
    }
}

// ---------------------------------------------------------------------------
// Fused Q+K projection: K-chunk 64, 3-stage cp.async. Tiles fully beyond
// len[b] skip all loads/MMA and just zero the Q tile (K never read there).
// ---------------------------------------------------------------------------
#define QK_AP 288
#define QK_WP 144
#define QK_STG 73728
#define PROJQK_SMEM (3 * QK_STG)

__global__ __launch_bounds__(512, 1) void proj_qk(
    const float* __restrict__ ctx, const int* __restrict__ lens)
{
    extern __shared__ char smraw[];
    const int tid  = threadIdx.x;
    const int lane = tid & 31;
    const int wid  = tid >> 5;
    const int wm   = wid >> 2;
    const int wn   = wid & 3;
    const int m0   = blockIdx.x * 128;
    const int lenb = lens[m0 >> 11];

    // Fully padded tile: zero Q (needed by attention), skip everything else.
    if ((m0 & 2047) >= lenb) {
        uint4 z = make_uint4(0, 0, 0, 0);
        #pragma unroll
        for (int i = 0; i < 4; i++) {
            int f = tid + i * 512;           // 2048 uint4 = 32KB
            int row = f >> 4, c = f & 15;
            *(uint4*)(g_Qf + (size_t)(m0 + row) * Dk + c * 8) = z;
        }
        return;
    }

    const uint32_t sbase = smem_u32(smraw);

    float acc[2][8][4];
    #pragma unroll
    for (int mt = 0; mt < 2; mt++)
        #pragma unroll
        for (int nt = 0; nt < 8; nt++)
            #pragma unroll
            for (int j = 0; j < 4; j++) acc[mt][nt][j] = 0.0f;

    const uint32_t b_row  = (uint32_t)((lane & 7) + ((lane >> 4) << 3));
    const uint32_t b_col2 = (uint32_t)((lane >> 3) & 1) * 16;

    auto copy_stage = [&](int stage, int k0) {
        const uint32_t st = sbase + stage * QK_STG;
        #pragma unroll
        for (int i = 0; i < 4; i++) {
            int f = tid + i * 512;
            int row = f >> 4, c = f & 15;
            cpa16(st + row * QK_AP + c * 16,
                  ctx + (size_t)(m0 + row) * Ee + k0 + c * 4);
        }
        #pragma unroll
        for (int i = 0; i < 4; i++) {
            int f = tid + i * 512;
            int row = f >> 3, q = f & 7;
            const __half* src = (row < 128)
                ? (g_Wt + (size_t)row * Ee)
                : (g_Wt + 131072 + (size_t)(row - 128) * Ee);
            cpa16(st + 36864 + row * QK_WP + q * 16, src + k0 + q * 8);
        }
    };

    auto do_mma = [&](int stage) {
        const char* smA = smraw + stage * QK_STG;
        const uint32_t stW = sbase + stage * QK_STG + 36864;
        #pragma unroll
        for (int ks = 0; ks < 4; ks++) {
            uint32_t af[2][4];
            #pragma unroll
            for (int mt = 0; mt < 2; mt++)
                a_frag_f32p(af[mt], smA, QK_AP, wm * 32 + mt * 16, ks * 16, lane);
            #pragma unroll
            for (int p = 0; p < 4; p++) {
                uint32_t nr = wn * 64 + p * 16 + b_row;
                uint32_t bh[4];
                LDMX4(bh, stW + nr * QK_WP + ks * 32 + b_col2);
                #pragma unroll
                for (int mt = 0; mt < 2; mt++) {
                    MMAF16(acc[mt][2*p],     af[mt], bh[0], bh[1]);
                    MMAF16(acc[mt][2*p + 1], af[mt], bh[2], bh[3]);
                }
            }
        }
    };

    copy_stage(0, 0);  CP_COMMIT;
    copy_stage(1, 64); CP_COMMIT;
    int stg = 0;
    for (int c = 0; c < 16; c++) {
        if (c < 14) { CP_WAIT(1); } else { CP_WAIT(0); }
        __syncthreads();
        if (c + 2 < 16) {
            copy_stage((stg + 2) % 3, (c + 2) * 64);
            CP_COMMIT;
        }
        do_mma(stg);
        stg = (stg + 1) % 3;
    }

    const bool isQ = (wn < 2);
    __half* C = isQ ? g_Qf : g_Kf;
    const int ncc = isQ ? wn * 64 : (wn - 2) * 64;
    const float sc = isQ ? (QSCALE / 32.0f) : (1.0f / 32.0f);
    #pragma unroll
    for (int mt = 0; mt < 2; mt++) {
        int r = m0 + wm * 32 + mt * 16 + (lane >> 2);
        float mk0 = ((((r)     & 2047) < lenb) ? 1.0f : 0.0f) * sc;
        float mk1 = ((((r + 8) & 2047) < lenb) ? 1.0f : 0.0f) * sc;
        #pragma unroll
        for (int nt = 0; nt < 8; nt++) {
            int cc = ncc + nt * 8 + (lane & 3) * 2;
            *(uint32_t*)(C + (size_t)r * Dk + cc) =
                pack_h2(acc[mt][nt][0] * mk0, acc[mt][nt][1] * mk0);
            *(uint32_t*)(C + (size_t)(r + 8) * Dk + cc) =
                pack_h2(acc[mt][nt][2] * mk1, acc[mt][nt][3] * mk1);
        }
    }
}

// ---------------------------------------------------------------------------
// V projection: cp.async 3-stage, chunk 32, 256 threads, 2 CTA/SM.
// Tiles fully beyond len[b] skip entirely (rows never read).
// ---------------------------------------------------------------------------
#define APITCH 160
#define PV_STG 30720
#define PROJV_SMEM (3 * PV_STG)

__global__ __launch_bounds__(256, 2) void proj_v(
    const float* __restrict__ x, const int* __restrict__ lens)
{
    extern __shared__ char smraw[];
    const int tid  = threadIdx.x;
    const int lane = tid & 31;
    const int wid  = tid >> 5;
    const int wm   = wid >> 1;
    const int wn   = wid & 1;
    const int m0   = blockIdx.x * 128;
    const int lenb = lens[m0 >> 11];
    if ((m0 & 2047) >= lenb) return;     // never read by attention or mean_v
    const __half* W = g_Wt + 2 * 131072;

    const uint32_t sbase = smem_u32(smraw);

    float acc[2][8][4];
    #pragma unroll
    for (int mt = 0; mt < 2; mt++)
        #pragma unroll
        for (int nt = 0; nt < 8; nt++)
            #pragma unroll
            for (int j = 0; j < 4; j++) acc[mt][nt][j] = 0.0f;

    const uint32_t b_row  = (uint32_t)((lane & 7) + ((lane >> 4) << 3));
    const uint32_t b_col2 = (uint32_t)((lane >> 3) & 1) * 16;

    auto copy_stage = [&](int stage, int k0) {
        const uint32_t st = sbase + stage * PV_STG;
        #pragma unroll
        for (int i = 0; i < 4; i++) {
            int f = tid + i * 256;
            int row = f >> 3, c = f & 7;
            cpa16(st + row * APITCH + c * 16,
                  x + (size_t)(m0 + row) * Ee + k0 + c * 4);
        }
        #pragma unroll
        for (int i = 0; i < 2; i++) {
            int f = tid + i * 256;
            int row = f >> 2, q = f & 3;
            cpa16(st + 20480 + row * 80 + q * 16,
                  W + (size_t)row * Ee + k0 + q * 8);
        }
    };

    auto do_mma = [&](int stage) {
        const char* smA = smraw + stage * PV_STG;
        const uint32_t stW = sbase + stage * PV_STG + 20480;
        #pragma unroll
        for (int ks = 0; ks < 2; ks++) {
            uint32_t af[2][4];
            #pragma unroll
            for (int mt = 0; mt < 2; mt++)
                a_frag_f32p(af[mt], smA, APITCH, wm * 32 + mt * 16, ks * 16, lane);
            #pragma unroll
            for (int p = 0; p < 4; p++) {
                uint32_t nr = wn * 64 + p * 16 + b_row;
                uint32_t bh[4];
                LDMX4(bh, stW + nr * 80 + ks * 32 + b_col2);
                #pragma unroll
                for (int mt = 0; mt < 2; mt++) {
                    MMAF16(acc[mt][2*p],     af[mt], bh[0], bh[1]);
                    MMAF16(acc[mt][2*p + 1], af[mt], bh[2], bh[3]);
                }
            }
        }
    };

    copy_stage(0, 0);  CP_COMMIT;
    copy_stage(1, 32); CP_COMMIT;
    int stg = 0;
    for (int c = 0; c < 32; c++) {
        if (c < 30) { CP_WAIT(1); } else { CP_WAIT(0); }
        __syncthreads();
        if (c + 2 < 32) {
            copy_stage((stg + 2) % 3, (c + 2) * 32);
            CP_COMMIT;
        }
        do_mma(stg);
        stg = (stg + 1) % 3;
    }

    const float sc = 1.0f / 32.0f;
    #pragma unroll
    for (int mt = 0; mt < 2; mt++) {
        int r = m0 + wm * 32 + mt * 16 + (lane >> 2);
        float mk0 = ((((r)     & 2047) < lenb) ? 1.0f : 0.0f) * sc;
        float mk1 = ((((r + 8) & 2047) < lenb) ? 1.0f : 0.0f) * sc;
        #pragma unroll
        for (int nt = 0; nt < 8; nt++) {
            int cc = wn * 64 + nt * 8 + (lane & 3) * 2;
            *(uint32_t*)(g_Vf + (size_t)r * Dk + cc) =
                pack_h2(acc[mt][nt][0] * mk0, acc[mt][nt][1] * mk0);
            *(uint32_t*)(g_Vf + (size_t)(r + 8) * Dk + cc) =
                pack_h2(acc[mt][nt][2] * mk1, acc[mt][nt][3] * mk1);
        }
    }
}

// ---------------------------------------------------------------------------
// Flash attention (R12 core): BQ=64, BK=64, 128 threads, 2 CTAs/SM.
// Fully-padded q-tiles (q0 >= len) broadcast g_meanV and exit.
// ---------------------------------------------------------------------------
#define AQP 272
#define SM_Qf 0
#define SM_K  17408
#define SM_V  52224
#define ATTN_SMEM 69632

__global__ __launch_bounds__(128, 2) void attn_mma(
    float* __restrict__ Out, const int* __restrict__ lens)
{
    extern __shared__ char sm[];
    const uint32_t sb = smem_u32(sm);
    const int tid  = threadIdx.x;
    const int lane = tid & 31;
    const int warp = tid >> 5;
    const int b    = blockIdx.x;
    const int q0   = (gridDim.y - 1 - blockIdx.y) * 64;
    const int len  = lens[b];

    // Fully padded query tile: all rows = mean of valid V rows.
    if (q0 >= len) {
        float4 mv[4];
        #pragma unroll
        for (int i = 0; i < 4; i++) {
            int d = (tid & 31) * 4 + (i & 1) * 128;   // not used; simple path below
        }
        // 64 rows x 32 float4; 128 threads -> 16 float4 each.
        #pragma unroll
        for (int i = 0; i < 16; i++) {
            int f = tid + i * 128;        // 0..2047
            int row = f >> 5, c4 = f & 31;
            float4 v = *(const float4*)(g_meanV + b * Dk + c4 * 4);
            *(float4*)(Out + ((size_t)(b * Ll + q0 + row)) * Dk + c4 * 4) = v;
        }
        return;
    }

    const uint32_t a_row = lane & 15;
    const uint32_t a_col = (uint32_t)(lane >> 4) * 16;
    const uint32_t b_row = (lane & 7) + ((lane >> 4) << 3);
    const uint32_t b_col = (uint32_t)((lane >> 3) & 1) * 16;
    const uint32_t v_k   = (lane & 7) + ((lane >> 3) & 1) * 8;
    const uint32_t v_d   = (uint32_t)(lane >> 4) * 16;

    auto copy_Q = [&]() {
        #pragma unroll
        for (int i = 0; i < 8; i++) {
            int f = tid + i * 128;
            int row = f >> 4, c = f & 15;
            cpa16(sb + SM_Qf + row * AQP + c * 16,
                  g_Qf + (size_t)(b * Ll + q0 + row) * Dk + c * 8);
        }
    };
    auto copy_K = [&](int stage, int j0) {
        const uint32_t kb = sb + SM_K + stage * 17408;
        #pragma unroll
        for (int i = 0; i < 8; i++) {
            int f = tid + i * 128;
            int row = f >> 4, c = f & 15;
            cpa16(kb + row * AQP + c * 16,
                  g_Kf + (size_t)(b * Ll + j0 + row) * Dk + c * 8);
        }
    };
    auto copy_V = [&](int j0) {
        #pragma unroll
        for (int i = 0; i < 8; i++) {
            int f = tid + i * 128;
            int row = f >> 4, c = f & 15;
            cpa16(sb + SM_V + row * AQP + c * 16,
                  g_Vf + (size_t)(b * Ll + j0 + row) * Dk + c * 8);
        }
    };

    float o[16][4];
    #pragma unroll
    for (int nt = 0; nt < 16; nt++)
        #pragma unroll
        for (int j = 0; j < 4; j++) o[nt][j] = 0.0f;
    float mrow[2] = {-1e30f, -1e30f};
    float lrow[2] = {0.0f, 0.0f};

    const int kend = min(len, q0 + 64);

    copy_Q();
    copy_K(0, 0);
    CP_COMMIT;
    CP_WAIT(0);
    __syncthreads();

    int cur = 0;
    for (int j0 = 0; j0 < kend; j0 += 64) {
        copy_V(j0);
        CP_COMMIT;

        float s[8][4];
        #pragma unroll
        for (int t = 0; t < 8; t++)
            #pragma unroll
            for (int j = 0; j < 4; j++) s[t][j] = 0.0f;

        const uint32_t kbase = sb + SM_K + cur * 17408;
        #pragma unroll
        for (int ks = 0; ks < 8; ks++) {
            uint32_t qf[4];
            LDMX4(qf, sb + SM_Qf + (warp * 16 + a_row) * AQP + ks * 32 + a_col);
            #pragma unroll
            for (int p = 0; p < 4; p++) {
                uint32_t bh[4];
                LDMX4(bh, kbase + (p * 16 + b_row) * AQP + ks * 32 + b_col);
                MMAF16(s[2*p],     qf, bh[0], bh[1]);
                MMAF16(s[2*p + 1], qf, bh[2], bh[3]);
            }
        }

        bool more = (j0 + 64 < kend);
        if (more) {
            copy_K(cur ^ 1, j0 + 64);
            CP_COMMIT;
            CP_WAIT(1);
        } else {
            CP_WAIT(0);
        }
        __syncthreads();

        const bool nomask = (j0 + 64 <= q0 + warp * 16 + 1) && (j0 + 64 <= len);

        #pragma unroll
        for (int h = 0; h < 2; h++) {
            const int qi = q0 + warp * 16 + (lane >> 2) + h * 8;
            float mx = -1e30f;
            if (nomask) {
                #pragma unroll
                for (int t = 0; t < 8; t++)
                    mx = fmaxf(mx, fmaxf(s[t][2*h], s[t][2*h + 1]));
            } else {
                #pragma unroll
                for (int t = 0; t < 8; t++) {
                    int c = j0 + t * 8 + (lane & 3) * 2;
                    float v0 = (c     <= qi && c     < len) ? s[t][2*h]     : -1e30f;
                    float v1 = (c + 1 <= qi && c + 1 < len) ? s[t][2*h + 1] : -1e30f;
                    s[t][2*h] = v0; s[t][2*h + 1] = v1;
                    mx = fmaxf(mx, fmaxf(v0, v1));
                }
            }
            mx = fmaxf(mx, __shfl_xor_sync(0xffffffffu, mx, 1));
            mx = fmaxf(mx, __shfl_xor_sync(0xffffffffu, mx, 2));
            float mnew = fmaxf(mrow[h], mx);
            float lsum = 0.0f;
            #pragma unroll
            for (int t = 0; t < 8; t++) {
                float p0 = exp2f(s[t][2*h]     - mnew);
                float p1 = exp2f(s[t][2*h + 1] - mnew);
                lsum += p0 + p1;
                s[t][2*h] = __uint_as_float(pack_h2(p0, p1));
            }
            lsum += __shfl_xor_sync(0xffffffffu, lsum, 1);
            lsum += __shfl_xor_sync(0xffffffffu, lsum, 2);
            if (mnew > mrow[h]) {
                float alpha = exp2f(mrow[h] - mnew);
                lrow[h] = lrow[h] * alpha + lsum;
                mrow[h] = mnew;
                #pragma unroll
                for (int nt = 0; nt < 16; nt++) {
                    o[nt][2*h]     *= alpha;
                    o[nt][2*h + 1] *= alpha;
                }
            } else {
                lrow[h] += lsum;
            }
        }

        #pragma unroll
        for (int ks = 0; ks < 4; ks++) {
            uint32_t pa[4];
            pa[0] = __float_as_uint(s[2*ks][0]);
            pa[1] = __float_as_uint(s[2*ks][2]);
            pa[2] = __float_as_uint(s[2*ks + 1][0]);
            pa[3] = __float_as_uint(s[2*ks + 1][2]);
            #pragma unroll
            for (int dt = 0; dt < 8; dt++) {
                uint32_t bh[4];
                LDMX4T(bh, sb + SM_V + (ks * 16 + v_k) * AQP + dt * 32 + v_d);
                MMAF16(o[2*dt],     pa, bh[0], bh[1]);
                MMAF16(o[2*dt + 1], pa, bh[2], bh[3]);
            }
        }
        CP_WAIT(0);
        __syncthreads();
        cur ^= 1;
    }

    #pragma unroll
    for (int h = 0; h < 2; h++) {
        float inv = 1.0f / lrow[h];
        int row = q0 + warp * 16 + (lane >> 2) + h * 8;
        float* og = Out + ((size_t)(b * Ll + row)) * Dk;
        #pragma unroll
        for (int dt = 0; dt < 16; dt++) {
            float2 v;
            v.x = o[dt][2*h]     * inv;
            v.y = o[dt][2*h + 1] * inv;
            *(float2*)(og + dt * 8 + (lane & 3) * 2) = v;
        }
    }
}

// ---------------------------------------------------------------------------
extern "C" void kernel_launch(void* const* d_in, const int* in_sizes, int n_in,
                              void* d_out, int out_size)
{
    const float* x    = (const float*)d_in[0];
    const float* ctx  = (const float*)d_in[1];
    const int*   lens = (const int*)  d_in[2];
    const float* Wq   = (const float*)d_in[3];
    const float* Wk   = (const float*)d_in[4];
    const float* Wv   = (const float*)d_in[5];
    float* out = (float*)d_out;
    (void)in_sizes; (void)n_in; (void)out_size;

    prep_weights<<<dim3(32, 4, 3), dim3(32, 32)>>>(Wq, Wk, Wv);

    cudaFuncSetAttribute(proj_qk,
                         cudaFuncAttributeMaxDynamicSharedMemorySize, PROJQK_SMEM);
    proj_qk<<<Mtot / 128, 512, PROJQK_SMEM>>>(ctx, lens);

    cudaFuncSetAttribute(proj_v,
                         cudaFuncAttributeMaxDynamicSharedMemorySize, PROJV_SMEM);
    proj_v<<<Mtot / 128, 256, PROJV_SMEM>>>(x, lens);

    mean_v<<<Bb, 512>>>(lens);

    cudaFuncSetAttribute(attn_mma,
                         cudaFuncAttributeMaxDynamicSharedMemorySize, ATTN_SMEM);
    attn_mma<<<dim3(Bb, Ll / 64), 128, ATTN_SMEM>>>(out, lens);
}

// round 17
// speedup vs baseline: 1.2365x; 1.2365x over previous
#include <cuda_runtime.h>
#include <cuda_fp16.h>
#include <cstdint>

#define Bb 16
#define Ll 2048
#define Ee 1024
#define Dk 128
#define Mtot (Bb*Ll)   // 32768

__device__ __half g_Qf[Mtot*Dk];
__device__ __half g_Kf[Mtot*Dk];
__device__ __half g_Vf[Mtot*Dk];
// Weights: [mat(3)][N=128][K=1024] fp16, pre-scaled by 32 (epilogue /32).
__device__ __half g_Wt[3 * 128 * 1024];
// Per-batch SUM of valid V rows (divided by len at broadcast time).
__device__ float g_sumV[Bb * Dk];

#define QSCALE 0.12751743f   /* log2(e)/sqrt(128) */

__device__ __forceinline__ uint32_t smem_u32(const void* p) {
    uint32_t a;
    asm("{ .reg .u64 t; cvta.to.shared.u64 t, %1; cvt.u32.u64 %0, t; }"
        : "=r"(a) : "l"(p));
    return a;
}

#define LDMX4(r, addr) \
    asm volatile("ldmatrix.sync.aligned.m8n8.x4.shared.b16 {%0,%1,%2,%3}, [%4];" \
        : "=r"((r)[0]), "=r"((r)[1]), "=r"((r)[2]), "=r"((r)[3]) : "r"(addr))

#define LDMX4T(r, addr) \
    asm volatile("ldmatrix.sync.aligned.m8n8.x4.trans.shared.b16 {%0,%1,%2,%3}, [%4];" \
        : "=r"((r)[0]), "=r"((r)[1]), "=r"((r)[2]), "=r"((r)[3]) : "r"(addr))

#define MMAF16(d, a, b0, b1) \
    asm volatile("mma.sync.aligned.m16n8k16.row.col.f32.f16.f16.f32 " \
        "{%0,%1,%2,%3}, {%4,%5,%6,%7}, {%8,%9}, {%0,%1,%2,%3};" \
        : "+f"((d)[0]), "+f"((d)[1]), "+f"((d)[2]), "+f"((d)[3]) \
        : "r"((a)[0]), "r"((a)[1]), "r"((a)[2]), "r"((a)[3]), "r"(b0), "r"(b1))

#define CP_COMMIT asm volatile("cp.async.commit_group;")
#define CP_WAIT(N) asm volatile("cp.async.wait_group %0;" :: "n"(N))

__device__ __forceinline__ void cpa16(uint32_t dst, const void* src) {
    asm volatile("cp.async.cg.shared.global [%0], [%1], 16;"
                 :: "r"(dst), "l"(src));
}

__device__ __forceinline__ uint32_t pack_h2(float x, float y) {
    __half2 h = __floats2half2_rn(x, y);
    return *(uint32_t*)&h;
}

// Assemble one m16n8k16 A-fragment (4 regs) from fp32 smem (given pitch).
__device__ __forceinline__ void a_frag_f32p(uint32_t* a, const char* smA,
                                            int pitch, int rb, int cb, int lane) {
    int r  = rb + (lane >> 2);
    int c  = cb + (lane & 3) * 2;
    float2 v0 = *(const float2*)(smA + r * pitch + c * 4);
    float2 v1 = *(const float2*)(smA + (r + 8) * pitch + c * 4);
    float2 v2 = *(const float2*)(smA + r * pitch + (c + 8) * 4);
    float2 v3 = *(const float2*)(smA + (r + 8) * pitch + (c + 8) * 4);
    a[0] = pack_h2(v0.x, v0.y);
    a[1] = pack_h2(v1.x, v1.y);
    a[2] = pack_h2(v2.x, v2.y);
    a[3] = pack_h2(v3.x, v3.y);
}

// ---------------------------------------------------------------------------
// Weight prep: W[1024,128] fp32 -> 32*W fp16, transposed [n][k].
// ---------------------------------------------------------------------------
__global__ void prep_weights(const float* __restrict__ Wq,
                             const float* __restrict__ Wk,
                             const float* __restrict__ Wv)
{
    __shared__ float t[32][33];
    const int mat = blockIdx.z;
    const float* W = (mat == 0) ? Wq : (mat == 1) ? Wk : Wv;
    const int k0 = blockIdx.x * 32, n0 = blockIdx.y * 32;
    const int tx = threadIdx.x, ty = threadIdx.y;
    t[ty][tx] = W[(size_t)(k0 + ty) * Dk + n0 + tx];
    __syncthreads();
    g_Wt[(size_t)mat * 131072 + (size_t)(n0 + ty) * Ee + k0 + tx] =
        __float2half_rn(t[tx][ty] * 32.0f);
}

// ---------------------------------------------------------------------------
// V-sum reduction, parallel: zero pass + (Bb x 16) partial CTAs via atomics.
// ---------------------------------------------------------------------------
__global__ void zero_sum()
{
    g_sumV[blockIdx.x * 1024 + threadIdx.x] = 0.0f;
}

__global__ void sum_v_part(const int* __restrict__ lens)
{
    const int b   = blockIdx.x;
    const int seg = blockIdx.y;            // 0..15 -> rows seg*128..+127
    const int len = lens[b];
    const int r0  = seg * 128;
    if (r0 >= len) return;
    const int r1  = min(len, r0 + 128);
    const int d   = threadIdx.x;           // 128 threads, one column each
    float s = 0.0f;
    for (int k = r0; k < r1; k++)
        s += __half2float(g_Vf[((size_t)(b * Ll + k)) * Dk + d]);
    atomicAdd(g_sumV + b * Dk + d, s);
}

// ---------------------------------------------------------------------------
// Fused Q+K projection: K-chunk 64, 3-stage cp.async. Tiles fully beyond
// len[b] skip all loads/MMA and just zero the Q tile (K never read there).
// ---------------------------------------------------------------------------
#define QK_AP 288
#define QK_WP 144
#define QK_STG 73728
#define PROJQK_SMEM (3 * QK_STG)

__global__ __launch_bounds__(512, 1) void proj_qk(
    const float* __restrict__ ctx, const int* __restrict__ lens)
{
    extern __shared__ char smraw[];
    const int tid  = threadIdx.x;
    const int lane = tid & 31;
    const int wid  = tid >> 5;
    const int wm   = wid >> 2;
    const int wn   = wid & 3;
    const int m0   = blockIdx.x * 128;
    const int lenb = lens[m0 >> 11];

    // Fully padded tile: zero Q (needed by attention), skip everything else.
    if ((m0 & 2047) >= lenb) {
        uint4 z = make_uint4(0, 0, 0, 0);
        #pragma unroll
        for (int i = 0; i < 4; i++) {
            int f = tid + i * 512;
            int row = f >> 4, c = f & 15;
            *(uint4*)(g_Qf + (size_t)(m0 + row) * Dk + c * 8) = z;
        }
        return;
    }

    const uint32_t sbase = smem_u32(smraw);

    float acc[2][8][4];
    #pragma unroll
    for (int mt = 0; mt < 2; mt++)
        #pragma unroll
        for (int nt = 0; nt < 8; nt++)
            #pragma unroll
            for (int j = 0; j < 4; j++) acc[mt][nt][j] = 0.0f;

    const uint32_t b_row  = (uint32_t)((lane & 7) + ((lane >> 4) << 3));
    const uint32_t b_col2 = (uint32_t)((lane >> 3) & 1) * 16;

    auto copy_stage = [&](int stage, int k0) {
        const uint32_t st = sbase + stage * QK_STG;
        #pragma unroll
        for (int i = 0; i < 4; i++) {
            int f = tid + i * 512;
            int row = f >> 4, c = f & 15;
            cpa16(st + row * QK_AP + c * 16,
                  ctx + (size_t)(m0 + row) * Ee + k0 + c * 4);
        }
        #pragma unroll
        for (int i = 0; i < 4; i++) {
            int f = tid + i * 512;
            int row = f >> 3, q = f & 7;
            const __half* src = (row < 128)
                ? (g_Wt + (size_t)row * Ee)
                : (g_Wt + 131072 + (size_t)(row - 128) * Ee);
            cpa16(st + 36864 + row * QK_WP + q * 16, src + k0 + q * 8);
        }
    };

    auto do_mma = [&](int stage) {
        const char* smA = smraw + stage * QK_STG;
        const uint32_t stW = sbase + stage * QK_STG + 36864;
        #pragma unroll
        for (int ks = 0; ks < 4; ks++) {
            uint32_t af[2][4];
            #pragma unroll
            for (int mt = 0; mt < 2; mt++)
                a_frag_f32p(af[mt], smA, QK_AP, wm * 32 + mt * 16, ks * 16, lane);
            #pragma unroll
            for (int p = 0; p < 4; p++) {
                uint32_t nr = wn * 64 + p * 16 + b_row;
                uint32_t bh[4];
                LDMX4(bh, stW + nr * QK_WP + ks * 32 + b_col2);
                #pragma unroll
                for (int mt = 0; mt < 2; mt++) {
                    MMAF16(acc[mt][2*p],     af[mt], bh[0], bh[1]);
                    MMAF16(acc[mt][2*p + 1], af[mt], bh[2], bh[3]);
                }
            }
        }
    };

    copy_stage(0, 0);  CP_COMMIT;
    copy_stage(1, 64); CP_COMMIT;
    int stg = 0;
    for (int c = 0; c < 16; c++) {
        if (c < 14) { CP_WAIT(1); } else { CP_WAIT(0); }
        __syncthreads();
        if (c + 2 < 16) {
            copy_stage((stg + 2) % 3, (c + 2) * 64);
            CP_COMMIT;
        }
        do_mma(stg);
        stg = (stg + 1) % 3;
    }

    const bool isQ = (wn < 2);
    __half* C = isQ ? g_Qf : g_Kf;
    const int ncc = isQ ? wn * 64 : (wn - 2) * 64;
    const float sc = isQ ? (QSCALE / 32.0f) : (1.0f / 32.0f);
    #pragma unroll
    for (int mt = 0; mt < 2; mt++) {
        int r = m0 + wm * 32 + mt * 16 + (lane >> 2);
        float mk0 = ((((r)     & 2047) < lenb) ? 1.0f : 0.0f) * sc;
        float mk1 = ((((r + 8) & 2047) < lenb) ? 1.0f : 0.0f) * sc;
        #pragma unroll
        for (int nt = 0; nt < 8; nt++) {
            int cc = ncc + nt * 8 + (lane & 3) * 2;
            *(uint32_t*)(C + (size_t)r * Dk + cc) =
                pack_h2(acc[mt][nt][0] * mk0, acc[mt][nt][1] * mk0);
            *(uint32_t*)(C + (size_t)(r + 8) * Dk + cc) =
                pack_h2(acc[mt][nt][2] * mk1, acc[mt][nt][3] * mk1);
        }
    }
}

// ---------------------------------------------------------------------------
// V projection: cp.async 3-stage, chunk 32, 256 threads, 2 CTA/SM.
// Tiles fully beyond len[b] skip entirely (rows never read).
// ---------------------------------------------------------------------------
#define APITCH 160
#define PV_STG 30720
#define PROJV_SMEM (3 * PV_STG)

__global__ __launch_bounds__(256, 2) void proj_v(
    const float* __restrict__ x, const int* __restrict__ lens)
{
    extern __shared__ char smraw[];
    const int tid  = threadIdx.x;
    const int lane = tid & 31;
    const int wid  = tid >> 5;
    const int wm   = wid >> 1;
    const int wn   = wid & 1;
    const int m0   = blockIdx.x * 128;
    const int lenb = lens[m0 >> 11];
    if ((m0 & 2047) >= lenb) return;     // never read downstream
    const __half* W = g_Wt + 2 * 131072;

    const uint32_t sbase = smem_u32(smraw);

    float acc[2][8][4];
    #pragma unroll
    for (int mt = 0; mt < 2; mt++)
        #pragma unroll
        for (int nt = 0; nt < 8; nt++)
            #pragma unroll
            for (int j = 0; j < 4; j++) acc[mt][nt][j] = 0.0f;

    const uint32_t b_row  = (uint32_t)((lane & 7) + ((lane >> 4) << 3));
    const uint32_t b_col2 = (uint32_t)((lane >> 3) & 1) * 16;

    auto copy_stage = [&](int stage, int k0) {
        const uint32_t st = sbase + stage * PV_STG;
        #pragma unroll
        for (int i = 0; i < 4; i++) {
            int f = tid + i * 256;
            int row = f >> 3, c = f & 7;
            cpa16(st + row * APITCH + c * 16,
                  x + (size_t)(m0 + row) * Ee + k0 + c * 4);
        }
        #pragma unroll
        for (int i = 0; i < 2; i++) {
            int f = tid + i * 256;
            int row = f >> 2, q = f & 3;
            cpa16(st + 20480 + row * 80 + q * 16,
                  W + (size_t)row * Ee + k0 + q * 8);
        }
    };

    auto do_mma = [&](int stage) {
        const char* smA = smraw + stage * PV_STG;
        const uint32_t stW = sbase + stage * PV_STG + 20480;
        #pragma unroll
        for (int ks = 0; ks < 2; ks++) {
            uint32_t af[2][4];
            #pragma unroll
            for (int mt = 0; mt < 2; mt++)
                a_frag_f32p(af[mt], smA, APITCH, wm * 32 + mt * 16, ks * 16, lane);
            #pragma unroll
            for (int p = 0; p < 4; p++) {
                uint32_t nr = wn * 64 + p * 16 + b_row;
                uint32_t bh[4];
                LDMX4(bh, stW + nr * 80 + ks * 32 + b_col2);
                #pragma unroll
                for (int mt = 0; mt < 2; mt++) {
                    MMAF16(acc[mt][2*p],     af[mt], bh[0], bh[1]);
                    MMAF16(acc[mt][2*p + 1], af[mt], bh[2], bh[3]);
                }
            }
        }
    };

    copy_stage(0, 0);  CP_COMMIT;
    copy_stage(1, 32); CP_COMMIT;
    int stg = 0;
    for (int c = 0; c < 32; c++) {
        if (c < 30) { CP_WAIT(1); } else { CP_WAIT(0); }
        __syncthreads();
        if (c + 2 < 32) {
            copy_stage((stg + 2) % 3, (c + 2) * 32);
            CP_COMMIT;
        }
        do_mma(stg);
        stg = (stg + 1) % 3;
    }

    const float sc = 1.0f / 32.0f;
    #pragma unroll
    for (int mt = 0; mt < 2; mt++) {
        int r = m0 + wm * 32 + mt * 16 + (lane >> 2);
        float mk0 = ((((r)     & 2047) < lenb) ? 1.0f : 0.0f) * sc;
        float mk1 = ((((r + 8) & 2047) < lenb) ? 1.0f : 0.0f) * sc;
        #pragma unroll
        for (int nt = 0; nt < 8; nt++) {
            int cc = wn * 64 + nt * 8 + (lane & 3) * 2;
            *(uint32_t*)(g_Vf + (size_t)r * Dk + cc) =
                pack_h2(acc[mt][nt][0] * mk0, acc[mt][nt][1] * mk0);
            *(uint32_t*)(g_Vf + (size_t)(r + 8) * Dk + cc) =
                pack_h2(acc[mt][nt][2] * mk1, acc[mt][nt][3] * mk1);
        }
    }
}

// ---------------------------------------------------------------------------
// Flash attention (R12 core): BQ=64, BK=64, 128 threads, 2 CTAs/SM.
// Fully-padded q-tiles (q0 >= len) broadcast g_sumV/len and exit.
// ---------------------------------------------------------------------------
#define AQP 272
#define SM_Qf 0
#define SM_K  17408
#define SM_V  52224
#define ATTN_SMEM 69632

__global__ __launch_bounds__(128, 2) void attn_mma(
    float* __restrict__ Out, const int* __restrict__ lens)
{
    extern __shared__ char sm[];
    const uint32_t sb = smem_u32(sm);
    const int tid  = threadIdx.x;
    const int lane = tid & 31;
    const int warp = tid >> 5;
    const int b    = blockIdx.x;
    const int q0   = (gridDim.y - 1 - blockIdx.y) * 64;
    const int len  = lens[b];

    // Fully padded query tile: all rows = sumV/len.
    if (q0 >= len) {
        const float inv = 1.0f / (float)len;
        #pragma unroll
        for (int i = 0; i < 16; i++) {
            int f = tid + i * 128;        // 0..2047 (64 rows x 32 float4)
            int row = f >> 5, c4 = f & 31;
            float4 v = *(const float4*)(g_sumV + b * Dk + c4 * 4);
            v.x *= inv; v.y *= inv; v.z *= inv; v.w *= inv;
            *(float4*)(Out + ((size_t)(b * Ll + q0 + row)) * Dk + c4 * 4) = v;
        }
        return;
    }

    const uint32_t a_row = lane & 15;
    const uint32_t a_col = (uint32_t)(lane >> 4) * 16;
    const uint32_t b_row = (lane & 7) + ((lane >> 4) << 3);
    const uint32_t b_col = (uint32_t)((lane >> 3) & 1) * 16;
    const uint32_t v_k   = (lane & 7) + ((lane >> 3) & 1) * 8;
    const uint32_t v_d   = (uint32_t)(lane >> 4) * 16;

    auto copy_Q = [&]() {
        #pragma unroll
        for (int i = 0; i < 8; i++) {
            int f = tid + i * 128;
            int row = f >> 4, c = f & 15;
            cpa16(sb + SM_Qf + row * AQP + c * 16,
                  g_Qf + (size_t)(b * Ll + q0 + row) * Dk + c * 8);
        }
    };
    auto copy_K = [&](int stage, int j0) {
        const uint32_t kb = sb + SM_K + stage * 17408;
        #pragma unroll
        for (int i = 0; i < 8; i++) {
            int f = tid + i * 128;
            int row = f >> 4, c = f & 15;
            cpa16(kb + row * AQP + c * 16,
                  g_Kf + (size_t)(b * Ll + j0 + row) * Dk + c * 8);
        }
    };
    auto copy_V = [&](int j0) {
        #pragma unroll
        for (int i = 0; i < 8; i++) {
            int f = tid + i * 128;
            int row = f >> 4, c = f & 15;
            cpa16(sb + SM_V + row * AQP + c * 16,
                  g_Vf + (size_t)(b * Ll + j0 + row) * Dk + c * 8);
        }
    };

    float o[16][4];
    #pragma unroll
    for (int nt = 0; nt < 16; nt++)
        #pragma unroll
        for (int j = 0; j < 4; j++) o[nt][j] = 0.0f;
    float mrow[2] = {-1e30f, -1e30f};
    float lrow[2] = {0.0f, 0.0f};

    const int kend = min(len, q0 + 64);

    copy_Q();
    copy_K(0, 0);
    CP_COMMIT;
    CP_WAIT(0);
    __syncthreads();

    int cur = 0;
    for (int j0 = 0; j0 < kend; j0 += 64) {
        copy_V(j0);
        CP_COMMIT;

        float s[8][4];
        #pragma unroll
        for (int t = 0; t < 8; t++)
            #pragma unroll
            for (int j = 0; j < 4; j++) s[t][j] = 0.0f;

        const uint32_t kbase = sb + SM_K + cur * 17408;
        #pragma unroll
        for (int ks = 0; ks < 8; ks++) {
            uint32_t qf[4];
            LDMX4(qf, sb + SM_Qf + (warp * 16 + a_row) * AQP + ks * 32 + a_col);
            #pragma unroll
            for (int p = 0; p < 4; p++) {
                uint32_t bh[4];
                LDMX4(bh, kbase + (p * 16 + b_row) * AQP + ks * 32 + b_col);
                MMAF16(s[2*p],     qf, bh[0], bh[1]);
                MMAF16(s[2*p + 1], qf, bh[2], bh[3]);
            }
        }

        bool more = (j0 + 64 < kend);
        if (more) {
            copy_K(cur ^ 1, j0 + 64);
            CP_COMMIT;
            CP_WAIT(1);
        } else {
            CP_WAIT(0);
        }
        __syncthreads();

        const bool nomask = (j0 + 64 <= q0 + warp * 16 + 1) && (j0 + 64 <= len);

        #pragma unroll
        for (int h = 0; h < 2; h++) {
            const int qi = q0 + warp * 16 + (lane >> 2) + h * 8;
            float mx = -1e30f;
            if (nomask) {
                #pragma unroll
                for (int t = 0; t < 8; t++)
                    mx = fmaxf(mx, fmaxf(s[t][2*h], s[t][2*h + 1]));
            } else {
                #pragma unroll
                for (int t = 0; t < 8; t++) {
                    int c = j0 + t * 8 + (lane & 3) * 2;
                    float v0 = (c     <= qi && c     < len) ? s[t][2*h]     : -1e30f;
                    float v1 = (c + 1 <= qi && c + 1 < len) ? s[t][2*h + 1] : -1e30f;
                    s[t][2*h] = v0; s[t][2*h + 1] = v1;
                    mx = fmaxf(mx, fmaxf(v0, v1));
                }
            }
            mx = fmaxf(mx, __shfl_xor_sync(0xffffffffu, mx, 1));
            mx = fmaxf(mx, __shfl_xor_sync(0xffffffffu, mx, 2));
            float mnew = fmaxf(mrow[h], mx);
            float lsum = 0.0f;
            #pragma unroll
            for (int t = 0; t < 8; t++) {
                float p0 = exp2f(s[t][2*h]     - mnew);
                float p1 = exp2f(s[t][2*h + 1] - mnew);
                lsum += p0 + p1;
                s[t][2*h] = __uint_as_float(pack_h2(p0, p1));
            }
            lsum += __shfl_xor_sync(0xffffffffu, lsum, 1);
            lsum += __shfl_xor_sync(0xffffffffu, lsum, 2);
            if (mnew > mrow[h]) {
                float alpha = exp2f(mrow[h] - mnew);
                lrow[h] = lrow[h] * alpha + lsum;
                mrow[h] = mnew;
                #pragma unroll
                for (int nt = 0; nt < 16; nt++) {
                    o[nt][2*h]     *= alpha;
                    o[nt][2*h + 1] *= alpha;
                }
            } else {
                lrow[h] += lsum;
            }
        }

        #pragma unroll
        for (int ks = 0; ks < 4; ks++) {
            uint32_t pa[4];
            pa[0] = __float_as_uint(s[2*ks][0]);
            pa[1] = __float_as_uint(s[2*ks][2]);
            pa[2] = __float_as_uint(s[2*ks + 1][0]);
            pa[3] = __float_as_uint(s[2*ks + 1][2]);
            #pragma unroll
            for (int dt = 0; dt < 8; dt++) {
                uint32_t bh[4];
                LDMX4T(bh, sb + SM_V + (ks * 16 + v_k) * AQP + dt * 32 + v_d);
                MMAF16(o[2*dt],     pa, bh[0], bh[1]);
                MMAF16(o[2*dt + 1], pa, bh[2], bh[3]);
            }
        }
        CP_WAIT(0);
        __syncthreads();
        cur ^= 1;
    }

    #pragma unroll
    for (int h = 0; h < 2; h++) {
        float inv = 1.0f / lrow[h];
        int row = q0 + warp * 16 + (lane >> 2) + h * 8;
        float* og = Out + ((size_t)(b * Ll + row)) * Dk;
        #pragma unroll
        for (int dt = 0; dt < 16; dt++) {
            float2 v;
            v.x = o[dt][2*h]     * inv;
            v.y = o[dt][2*h + 1] * inv;
            *(float2*)(og + dt * 8 + (lane & 3) * 2) = v;
        }
    }
}

// ---------------------------------------------------------------------------
extern "C" void kernel_launch(void* const* d_in, const int* in_sizes, int n_in,
                              void* d_out, int out_size)
{
    const float* x    = (const float*)d_in[0];
    const float* ctx  = (const float*)d_in[1];
    const int*   lens = (const int*)  d_in[2];
    const float* Wq   = (const float*)d_in[3];
    const float* Wk   = (const float*)d_in[4];
    const float* Wv   = (const float*)d_in[5];
    float* out = (float*)d_out;
    (void)in_sizes; (void)n_in; (void)out_size;

    prep_weights<<<dim3(32, 4, 3), dim3(32, 32)>>>(Wq, Wk, Wv);

    cudaFuncSetAttribute(proj_qk,
                         cudaFuncAttributeMaxDynamicSharedMemorySize, PROJQK_SMEM);
    proj_qk<<<Mtot / 128, 512, PROJQK_SMEM>>>(ctx, lens);

    cudaFuncSetAttribute(proj_v,
                         cudaFuncAttributeMaxDynamicSharedMemorySize, PROJV_SMEM);
    proj_v<<<Mtot / 128, 256, PROJV_SMEM>>>(x, lens);

    zero_sum<<<2, 1024>>>();
    sum_v_part<<<dim3(Bb, 16), 128>>>(lens);

    cudaFuncSetAttribute(attn_mma,
                         cudaFuncAttributeMaxDynamicSharedMemorySize, ATTN_SMEM);
    attn_mma<<<dim3(Bb, Ll / 64), 128, ATTN_SMEM>>>(out, lens);
}